// round 5
// baseline (speedup 1.0000x reference)
#include <cuda_runtime.h>
#include <math.h>
#include <stdint.h>

#define N 256
#define NT (N*N)
#define C 128
#define H 4
#define D 32

// -------- scratch (device globals; no allocation allowed) --------
__device__ float    g_lnz[NT*C];      // plain LN output (bias kernel)
__device__ uint32_t g_lnzh[NT*C];     // LN output, tf32 hi
__device__ uint32_t g_lnzl[NT*C];     // LN output, tf32 lo
__device__ float    g_q[NT*C];
__device__ float    g_k[NT*C];
__device__ float    g_v[NT*C];
__device__ float    g_g[NT*C];        // sigmoid(z@Wg)
__device__ float    g_bt[H*NT];       // bias transposed: [h][k][j]
__device__ uint32_t g_oh[NT*C];       // gated attn output, tf32 hi
__device__ uint32_t g_ol[NT*C];       // gated attn output, tf32 lo
__device__ uint32_t g_wh[5*C*C];      // 5 weight matrices, tf32 hi
__device__ uint32_t g_wl[5*C*C];      // 5 weight matrices, tf32 lo

__device__ __forceinline__ void split_tf32(float x, uint32_t& hi, uint32_t& lo) {
    asm("cvt.rna.tf32.f32 %0, %1;" : "=r"(hi) : "f"(x));
    float r = x - __uint_as_float(hi);
    asm("cvt.rna.tf32.f32 %0, %1;" : "=r"(lo) : "f"(r));
}
__device__ __forceinline__ uint32_t to_tf32(float x) {
    uint32_t u;
    asm("cvt.rna.tf32.f32 %0, %1;" : "=r"(u) : "f"(x));
    return u;
}
__device__ __forceinline__ void mma_tf32(float* c, const uint32_t* a,
                                         const uint32_t* b) {
    asm volatile(
        "mma.sync.aligned.m16n8k8.row.col.f32.tf32.tf32.f32 "
        "{%0,%1,%2,%3},{%4,%5,%6,%7},{%8,%9},{%0,%1,%2,%3};"
        : "+f"(c[0]), "+f"(c[1]), "+f"(c[2]), "+f"(c[3])
        : "r"(a[0]), "r"(a[1]), "r"(a[2]), "r"(a[3]), "r"(b[0]), "r"(b[1]));
}
__device__ __forceinline__ void cp16(uint32_t* smem_dst, const void* gsrc) {
    uint32_t s = (uint32_t)__cvta_generic_to_shared(smem_dst);
    asm volatile("cp.async.cg.shared.global [%0], [%1], 16;\n"
                 :: "r"(s), "l"(gsrc));
}

// ---------------- LayerNorm: one warp per token; writes plain + split ----------------
__global__ void ln_kernel(const float* __restrict__ z,
                          const float* __restrict__ gamma,
                          const float* __restrict__ beta) {
    int warp = threadIdx.x >> 5, lane = threadIdx.x & 31;
    int t = blockIdx.x * 8 + warp;
    const float4 v = *(const float4*)(z + (size_t)t * C + lane * 4);
    float s = v.x + v.y + v.z + v.w;
    #pragma unroll
    for (int o = 16; o; o >>= 1) s += __shfl_xor_sync(0xffffffffu, s, o);
    float mu = s * (1.0f / C);
    float d0 = v.x - mu, d1 = v.y - mu, d2 = v.z - mu, d3 = v.w - mu;
    float vs = d0*d0 + d1*d1 + d2*d2 + d3*d3;
    #pragma unroll
    for (int o = 16; o; o >>= 1) vs += __shfl_xor_sync(0xffffffffu, vs, o);
    float r = rsqrtf(vs * (1.0f / C) + 1e-5f);
    float4 gm = *(const float4*)(gamma + lane * 4);
    float4 bt = *(const float4*)(beta + lane * 4);
    float o0 = d0 * r * gm.x + bt.x;
    float o1 = d1 * r * gm.y + bt.y;
    float o2 = d2 * r * gm.z + bt.z;
    float o3 = d3 * r * gm.w + bt.w;
    size_t idx = (size_t)t * C + lane * 4;
    *(float4*)(g_lnz + idx) = make_float4(o0, o1, o2, o3);
    uint4 hv, lv;
    split_tf32(o0, hv.x, lv.x);
    split_tf32(o1, hv.y, lv.y);
    split_tf32(o2, hv.z, lv.z);
    split_tf32(o3, hv.w, lv.w);
    *(uint4*)(g_lnzh + idx) = hv;
    *(uint4*)(g_lnzl + idx) = lv;
}

// ---------------- weight pre-split ----------------
__global__ void wsplit_kernel(const float* __restrict__ W, int slot) {
    int i = blockIdx.x * 256 + threadIdx.x;
    uint32_t h, l;
    split_tf32(W[i], h, l);
    g_wh[slot * C * C + i] = h;
    g_wl[slot * C * C + i] = l;
}

// ---------------- pre-split 3xTF32 GEMM with cp.async pipeline ----------------
// Y[NT,128] = X[NT,128] @ W[128,128]; X,W given as tf32 hi/lo words.
#define XS 36
#define WS 132
#define STG_X (128 * XS)
#define STG_W (32 * WS)
#define STG_WORDS (2 * STG_X + 2 * STG_W)
#define GEMM_SMEM (2 * STG_WORDS * 4)

__global__ void __launch_bounds__(256)
gemm_ps(const uint32_t* __restrict__ Xh, const uint32_t* __restrict__ Xl,
        const uint32_t* __restrict__ Wh, const uint32_t* __restrict__ Wl,
        float* __restrict__ Y, int sigm) {
    extern __shared__ uint32_t sm4[];
    int tid = threadIdx.x;
    int warp = tid >> 5, lane = tid & 31;
    int g = lane >> 2, t = lane & 3;
    int warp_m = warp >> 2, warp_n = warp & 3;
    int row0 = blockIdx.x * 128;

    // prefetch issue for k-chunk kc into stage s
    auto issue = [&](int kc, int s) {
        uint32_t* xh = sm4 + s * STG_WORDS;
        uint32_t* xl = xh + STG_X;
        uint32_t* wh = xl + STG_X;
        uint32_t* wl = wh + STG_W;
        #pragma unroll
        for (int i = 0; i < 4; i++) {
            int id = tid + i * 256;
            int row = id >> 3, c4 = (id & 7) * 4;
            size_t go = (size_t)(row0 + row) * C + kc * 32 + c4;
            cp16(xh + row * XS + c4, Xh + go);
            cp16(xl + row * XS + c4, Xl + go);
        }
        #pragma unroll
        for (int i = 0; i < 4; i++) {
            int id = tid + i * 256;
            int k = id >> 5, c4 = (id & 31) * 4;
            size_t go = (size_t)(kc * 32 + k) * C + c4;
            cp16(wh + k * WS + c4, Wh + go);
            cp16(wl + k * WS + c4, Wl + go);
        }
    };

    float c[4][4][4];
    #pragma unroll
    for (int mb = 0; mb < 4; mb++)
        #pragma unroll
        for (int nb = 0; nb < 4; nb++)
            #pragma unroll
            for (int r = 0; r < 4; r++) c[mb][nb][r] = 0.0f;

    issue(0, 0);
    asm volatile("cp.async.commit_group;\n");

    for (int kc = 0; kc < 4; kc++) {
        if (kc + 1 < 4) {
            issue(kc + 1, (kc + 1) & 1);
            asm volatile("cp.async.commit_group;\n");
            asm volatile("cp.async.wait_group 1;\n");
        } else {
            asm volatile("cp.async.wait_group 0;\n");
        }
        __syncthreads();

        uint32_t* xh = sm4 + (kc & 1) * STG_WORDS;
        uint32_t* xl = xh + STG_X;
        uint32_t* wh = xl + STG_X;
        uint32_t* wl = wh + STG_W;

        #pragma unroll
        for (int ks = 0; ks < 4; ks++) {
            int kk = ks * 8;
            uint32_t bh[4][2], bl[4][2];
            #pragma unroll
            for (int nb = 0; nb < 4; nb++) {
                int n = warp_n * 32 + nb * 8 + g;
                bh[nb][0] = wh[(kk + t) * WS + n];
                bh[nb][1] = wh[(kk + t + 4) * WS + n];
                bl[nb][0] = wl[(kk + t) * WS + n];
                bl[nb][1] = wl[(kk + t + 4) * WS + n];
            }
            #pragma unroll
            for (int mb = 0; mb < 4; mb++) {
                int r = warp_m * 64 + mb * 16 + g;
                uint32_t ah[4], al[4];
                ah[0] = xh[r * XS + kk + t];
                ah[1] = xh[(r + 8) * XS + kk + t];
                ah[2] = xh[r * XS + kk + t + 4];
                ah[3] = xh[(r + 8) * XS + kk + t + 4];
                al[0] = xl[r * XS + kk + t];
                al[1] = xl[(r + 8) * XS + kk + t];
                al[2] = xl[r * XS + kk + t + 4];
                al[3] = xl[(r + 8) * XS + kk + t + 4];
                #pragma unroll
                for (int nb = 0; nb < 4; nb++) {
                    mma_tf32(c[mb][nb], ah, bh[nb]);
                    mma_tf32(c[mb][nb], ah, bl[nb]);
                    mma_tf32(c[mb][nb], al, bh[nb]);
                }
            }
        }
        __syncthreads();
    }

    #pragma unroll
    for (int mb = 0; mb < 4; mb++) {
        int r0 = row0 + warp_m * 64 + mb * 16 + g;
        #pragma unroll
        for (int nb = 0; nb < 4; nb++) {
            int col = warp_n * 32 + nb * 8 + 2 * t;
            float v0 = c[mb][nb][0], v1 = c[mb][nb][1];
            float v2 = c[mb][nb][2], v3 = c[mb][nb][3];
            if (sigm) {
                v0 = 1.0f / (1.0f + __expf(-v0));
                v1 = 1.0f / (1.0f + __expf(-v1));
                v2 = 1.0f / (1.0f + __expf(-v2));
                v3 = 1.0f / (1.0f + __expf(-v3));
            }
            *(float2*)(Y + (size_t)r0 * C + col) = make_float2(v0, v1);
            *(float2*)(Y + (size_t)(r0 + 8) * C + col) = make_float2(v2, v3);
        }
    }
}

// ------- bias = lnz @ Wb, written TRANSPOSED as g_bt[h][k][j] -------
__global__ void bias_kernel(const float* __restrict__ Wb) {
    __shared__ float wb[C * H];
    int tid = threadIdx.x;
    wb[tid] = Wb[tid];
    wb[tid + 256] = Wb[tid + 256];
    __syncthreads();
    int warp = tid >> 5, lane = tid & 31;
    int t = blockIdx.x * 8 + warp;
    float4 zv = *(const float4*)(g_lnz + (size_t)t * C + lane * 4);
    int c0 = lane * 4;
    int j = t >> 8, k = t & 255;
    #pragma unroll
    for (int h = 0; h < H; h++) {
        float p = zv.x * wb[(c0 + 0) * H + h] + zv.y * wb[(c0 + 1) * H + h] +
                  zv.z * wb[(c0 + 2) * H + h] + zv.w * wb[(c0 + 3) * H + h];
        #pragma unroll
        for (int o = 16; o; o >>= 1) p += __shfl_xor_sync(0xffffffffu, p, o);
        if (lane == 0) g_bt[((size_t)h * N + k) * N + j] = p;
    }
}

// ---------------- tensor-core attention (epilogue writes split O) ----------------
#define KTS 260
#define VST 36
#define PST 36
#define ATTN_SMEM ((2 * 32 * KTS + 256 * VST + 8 * 32 * PST) * 4)

__global__ void __launch_bounds__(256)
attn_mma() {
    extern __shared__ float sm[];
    float* Kht = sm;
    float* Klt = Kht + 32 * KTS;
    float* Vs  = Klt + 32 * KTS;
    float* Ps  = Vs + 256 * VST;

    int i = blockIdx.x, h = blockIdx.y;
    int tid = threadIdx.x;
    int w = tid >> 5, lane = tid & 31;
    int g = lane >> 2, t = lane & 3;
    size_t base = (size_t)i * N;
    int coff = h * D;
    float* Pw = Ps + w * 32 * PST;
    const float sc = 0.17677669529663687f;

    #pragma unroll
    for (int it = 0; it < 8; it++) {
        int idx = tid + it * 256;
        int tok = idx >> 3, f = idx & 7;
        float4 kv = *(const float4*)(g_k + (base + tok) * C + coff + f * 4);
        uint32_t hx, lx;
        split_tf32(kv.x, hx, lx);
        Kht[(f*4+0)*KTS + tok] = __uint_as_float(hx);
        Klt[(f*4+0)*KTS + tok] = __uint_as_float(lx);
        split_tf32(kv.y, hx, lx);
        Kht[(f*4+1)*KTS + tok] = __uint_as_float(hx);
        Klt[(f*4+1)*KTS + tok] = __uint_as_float(lx);
        split_tf32(kv.z, hx, lx);
        Kht[(f*4+2)*KTS + tok] = __uint_as_float(hx);
        Klt[(f*4+2)*KTS + tok] = __uint_as_float(lx);
        split_tf32(kv.w, hx, lx);
        Kht[(f*4+3)*KTS + tok] = __uint_as_float(hx);
        Klt[(f*4+3)*KTS + tok] = __uint_as_float(lx);

        float4 vv = *(const float4*)(g_v + (base + tok) * C + coff + f * 4);
        float4 vt;
        vt.x = __uint_as_float(to_tf32(vv.x));
        vt.y = __uint_as_float(to_tf32(vv.y));
        vt.z = __uint_as_float(to_tf32(vv.z));
        vt.w = __uint_as_float(to_tf32(vv.w));
        *(float4*)(Vs + tok * VST + f * 4) = vt;
    }

    int jb = w * 32;
    uint32_t qh[2][4][4], ql[2][4][4];
    #pragma unroll
    for (int mb = 0; mb < 2; mb++) {
        int r1 = jb + mb * 16 + g, r2 = r1 + 8;
        #pragma unroll
        for (int ds = 0; ds < 4; ds++) {
            int c1 = coff + ds * 8 + t, c2 = c1 + 4;
            float q0 = g_q[(base + r1) * C + c1] * sc;
            float q1 = g_q[(base + r2) * C + c1] * sc;
            float q2 = g_q[(base + r1) * C + c2] * sc;
            float q3 = g_q[(base + r2) * C + c2] * sc;
            split_tf32(q0, qh[mb][ds][0], ql[mb][ds][0]);
            split_tf32(q1, qh[mb][ds][1], ql[mb][ds][1]);
            split_tf32(q2, qh[mb][ds][2], ql[mb][ds][2]);
            split_tf32(q3, qh[mb][ds][3], ql[mb][ds][3]);
        }
    }
    __syncthreads();

    float o[2][4][4];
    #pragma unroll
    for (int mb = 0; mb < 2; mb++)
        #pragma unroll
        for (int nb = 0; nb < 4; nb++)
            #pragma unroll
            for (int r = 0; r < 4; r++) o[mb][nb][r] = 0.0f;
    float lA[2] = {0.f, 0.f}, lB[2] = {0.f, 0.f};

    const float* bth = g_bt + (size_t)h * NT;

    for (int ch = 0; ch < 8; ch++) {
        int tok0 = ch * 32;
        float s[2][4][4];
        #pragma unroll
        for (int mb = 0; mb < 2; mb++)
            #pragma unroll
            for (int nt = 0; nt < 4; nt++)
                #pragma unroll
                for (int r = 0; r < 4; r++) s[mb][nt][r] = 0.0f;

        #pragma unroll
        for (int nt = 0; nt < 4; nt++) {
            int tokn = tok0 + nt * 8 + g;
            #pragma unroll
            for (int ds = 0; ds < 4; ds++) {
                uint32_t bh2[2], bl2[2];
                bh2[0] = __float_as_uint(Kht[(ds*8 + t) * KTS + tokn]);
                bh2[1] = __float_as_uint(Kht[(ds*8 + t + 4) * KTS + tokn]);
                bl2[0] = __float_as_uint(Klt[(ds*8 + t) * KTS + tokn]);
                bl2[1] = __float_as_uint(Klt[(ds*8 + t + 4) * KTS + tokn]);
                #pragma unroll
                for (int mb = 0; mb < 2; mb++) {
                    mma_tf32(s[mb][nt], qh[mb][ds], bh2);
                    mma_tf32(s[mb][nt], qh[mb][ds], bl2);
                    mma_tf32(s[mb][nt], ql[mb][ds], bh2);
                }
            }
        }
        #pragma unroll
        for (int mb = 0; mb < 2; mb++) {
            int j1 = jb + mb * 16 + g, j2 = j1 + 8;
            #pragma unroll
            for (int nt = 0; nt < 4; nt++) {
                int k0 = tok0 + nt * 8 + 2 * t;
                float b00 = bth[(size_t)k0 * N + j1];
                float b01 = bth[(size_t)(k0 + 1) * N + j1];
                float b10 = bth[(size_t)k0 * N + j2];
                float b11 = bth[(size_t)(k0 + 1) * N + j2];
                float p0 = __expf(s[mb][nt][0] + b00);
                float p1 = __expf(s[mb][nt][1] + b01);
                float p2 = __expf(s[mb][nt][2] + b10);
                float p3 = __expf(s[mb][nt][3] + b11);
                lA[mb] += p0 + p1;
                lB[mb] += p2 + p3;
                int cc = nt * 8 + 2 * t;
                Pw[(mb*16 + g) * PST + cc]     = __uint_as_float(to_tf32(p0));
                Pw[(mb*16 + g) * PST + cc + 1] = __uint_as_float(to_tf32(p1));
                Pw[(mb*16 + 8 + g) * PST + cc]     = __uint_as_float(to_tf32(p2));
                Pw[(mb*16 + 8 + g) * PST + cc + 1] = __uint_as_float(to_tf32(p3));
            }
        }
        __syncwarp();
        #pragma unroll
        for (int ks = 0; ks < 4; ks++) {
            uint32_t pa[2][4];
            #pragma unroll
            for (int mb = 0; mb < 2; mb++) {
                pa[mb][0] = __float_as_uint(Pw[(mb*16 + g) * PST + ks*8 + t]);
                pa[mb][1] = __float_as_uint(Pw[(mb*16 + 8 + g) * PST + ks*8 + t]);
                pa[mb][2] = __float_as_uint(Pw[(mb*16 + g) * PST + ks*8 + t + 4]);
                pa[mb][3] = __float_as_uint(Pw[(mb*16 + 8 + g) * PST + ks*8 + t + 4]);
            }
            #pragma unroll
            for (int nb = 0; nb < 4; nb++) {
                uint32_t vb[2];
                vb[0] = __float_as_uint(Vs[(tok0 + ks*8 + t) * VST + nb*8 + g]);
                vb[1] = __float_as_uint(Vs[(tok0 + ks*8 + t + 4) * VST + nb*8 + g]);
                #pragma unroll
                for (int mb = 0; mb < 2; mb++)
                    mma_tf32(o[mb][nb], pa[mb], vb);
            }
        }
        __syncwarp();
    }

    // ---- normalize, gate, split-store ----
    #pragma unroll
    for (int mb = 0; mb < 2; mb++) {
        lA[mb] += __shfl_xor_sync(0xffffffffu, lA[mb], 1);
        lA[mb] += __shfl_xor_sync(0xffffffffu, lA[mb], 2);
        lB[mb] += __shfl_xor_sync(0xffffffffu, lB[mb], 1);
        lB[mb] += __shfl_xor_sync(0xffffffffu, lB[mb], 2);
        float inv1 = 1.0f / lA[mb], inv2 = 1.0f / lB[mb];
        int j1 = jb + mb * 16 + g, j2 = j1 + 8;
        #pragma unroll
        for (int nb = 0; nb < 4; nb++) {
            int d = nb * 8 + 2 * t;
            float2 g1 = *(const float2*)(g_g + (base + j1) * C + coff + d);
            float2 g2 = *(const float2*)(g_g + (base + j2) * C + coff + d);
            float o1x = g1.x * o[mb][nb][0] * inv1;
            float o1y = g1.y * o[mb][nb][1] * inv1;
            float o2x = g2.x * o[mb][nb][2] * inv2;
            float o2y = g2.y * o[mb][nb][3] * inv2;
            uint2 h1, l1, h2, l2;
            split_tf32(o1x, h1.x, l1.x);
            split_tf32(o1y, h1.y, l1.y);
            split_tf32(o2x, h2.x, l2.x);
            split_tf32(o2y, h2.y, l2.y);
            size_t i1 = (base + j1) * C + coff + d;
            size_t i2 = (base + j2) * C + coff + d;
            *(uint2*)(g_oh + i1) = h1;
            *(uint2*)(g_ol + i1) = l1;
            *(uint2*)(g_oh + i2) = h2;
            *(uint2*)(g_ol + i2) = l2;
        }
    }
}

extern "C" void kernel_launch(void* const* d_in, const int* in_sizes, int n_in,
                              void* d_out, int out_size) {
    const float* z     = (const float*)d_in[0];
    const float* gamma = (const float*)d_in[1];
    const float* beta  = (const float*)d_in[2];
    const float* Wq    = (const float*)d_in[3];
    const float* Wk    = (const float*)d_in[4];
    const float* Wv    = (const float*)d_in[5];
    const float* Wb    = (const float*)d_in[6];
    const float* Wg    = (const float*)d_in[7];
    const float* Wout  = (const float*)d_in[8];
    float* out = (float*)d_out;

    void *p_lnzh, *p_lnzl, *p_q, *p_k, *p_v, *p_g, *p_oh, *p_ol, *p_wh, *p_wl;
    cudaGetSymbolAddress(&p_lnzh, g_lnzh);
    cudaGetSymbolAddress(&p_lnzl, g_lnzl);
    cudaGetSymbolAddress(&p_q, g_q);
    cudaGetSymbolAddress(&p_k, g_k);
    cudaGetSymbolAddress(&p_v, g_v);
    cudaGetSymbolAddress(&p_g, g_g);
    cudaGetSymbolAddress(&p_oh, g_oh);
    cudaGetSymbolAddress(&p_ol, g_ol);
    cudaGetSymbolAddress(&p_wh, g_wh);
    cudaGetSymbolAddress(&p_wl, g_wl);

    const uint32_t* xh = (const uint32_t*)p_lnzh;
    const uint32_t* xl = (const uint32_t*)p_lnzl;
    const uint32_t* wh = (const uint32_t*)p_wh;
    const uint32_t* wl = (const uint32_t*)p_wl;

    cudaFuncSetAttribute(gemm_ps,
                         cudaFuncAttributeMaxDynamicSharedMemorySize, GEMM_SMEM);
    cudaFuncSetAttribute(attn_mma,
                         cudaFuncAttributeMaxDynamicSharedMemorySize, ATTN_SMEM);

    ln_kernel<<<NT / 8, 256>>>(z, gamma, beta);
    wsplit_kernel<<<64, 256>>>(Wq, 0);
    wsplit_kernel<<<64, 256>>>(Wk, 1);
    wsplit_kernel<<<64, 256>>>(Wv, 2);
    wsplit_kernel<<<64, 256>>>(Wg, 3);
    wsplit_kernel<<<64, 256>>>(Wout, 4);

    gemm_ps<<<NT / 128, 256, GEMM_SMEM>>>(xh, xl, wh + 0*C*C, wl + 0*C*C, (float*)p_q, 0);
    gemm_ps<<<NT / 128, 256, GEMM_SMEM>>>(xh, xl, wh + 1*C*C, wl + 1*C*C, (float*)p_k, 0);
    gemm_ps<<<NT / 128, 256, GEMM_SMEM>>>(xh, xl, wh + 2*C*C, wl + 2*C*C, (float*)p_v, 0);
    gemm_ps<<<NT / 128, 256, GEMM_SMEM>>>(xh, xl, wh + 3*C*C, wl + 3*C*C, (float*)p_g, 1);
    bias_kernel<<<NT / 8, 256>>>(Wb);
    attn_mma<<<dim3(N, H), 256, ATTN_SMEM>>>();
    gemm_ps<<<NT / 128, 256, GEMM_SMEM>>>((const uint32_t*)p_oh, (const uint32_t*)p_ol,
                                          wh + 4*C*C, wl + 4*C*C, out, 0);
}

// round 6
// speedup vs baseline: 1.4076x; 1.4076x over previous
#include <cuda_runtime.h>
#include <cuda_bf16.h>
#include <math.h>
#include <stdint.h>

#define N 256
#define NT (N*N)
#define C 128
#define H 4
#define D 32

// -------- scratch (device globals; no allocation allowed) --------
__device__ float    g_lnz[NT*C];
__device__ float    g_q[NT*C];
__device__ float    g_k[NT*C];
__device__ float    g_v[NT*C];
__device__ float    g_g[NT*C];     // sigmoid(z@Wg)
__device__ float    g_bt[H*NT];    // bias transposed: [h][k][j]
__device__ float    g_o[NT*C];     // gated attention output
// packed-transposed split weights: [mat][n][k2] bf16 pairs (k even low, odd high)
__device__ uint32_t g_wph[5*C*(C/2)];
__device__ uint32_t g_wpl[5*C*(C/2)];

struct Y4 { float* p[4]; };
struct W5 { const float* w[5]; };

// ---------- helpers ----------
__device__ __forceinline__ float bf16val(float x) {
    return __bfloat162float(__float2bfloat16(x));
}
__device__ __forceinline__ uint32_t bf16pair(float even, float odd) {
    uint32_t r;
    asm("cvt.rn.satfinite.bf16x2.f32 %0, %1, %2;" : "=r"(r) : "f"(odd), "f"(even));
    return r;
}
__device__ __forceinline__ void mma_bf16(float* c, const uint32_t* a,
                                         const uint32_t* b) {
    asm volatile(
        "mma.sync.aligned.m16n8k16.row.col.f32.bf16.bf16.f32 "
        "{%0,%1,%2,%3},{%4,%5,%6,%7},{%8,%9},{%0,%1,%2,%3};"
        : "+f"(c[0]), "+f"(c[1]), "+f"(c[2]), "+f"(c[3])
        : "r"(a[0]), "r"(a[1]), "r"(a[2]), "r"(a[3]), "r"(b[0]), "r"(b[1]));
}
__device__ __forceinline__ void split_tf32(float x, uint32_t& hi, uint32_t& lo) {
    asm("cvt.rna.tf32.f32 %0, %1;" : "=r"(hi) : "f"(x));
    float r = x - __uint_as_float(hi);
    asm("cvt.rna.tf32.f32 %0, %1;" : "=r"(lo) : "f"(r));
}
__device__ __forceinline__ uint32_t to_tf32(float x) {
    uint32_t u;
    asm("cvt.rna.tf32.f32 %0, %1;" : "=r"(u) : "f"(x));
    return u;
}
__device__ __forceinline__ void mma_tf32(float* c, const uint32_t* a,
                                         const uint32_t* b) {
    asm volatile(
        "mma.sync.aligned.m16n8k8.row.col.f32.tf32.tf32.f32 "
        "{%0,%1,%2,%3},{%4,%5,%6,%7},{%8,%9},{%0,%1,%2,%3};"
        : "+f"(c[0]), "+f"(c[1]), "+f"(c[2]), "+f"(c[3])
        : "r"(a[0]), "r"(a[1]), "r"(a[2]), "r"(a[3]), "r"(b[0]), "r"(b[1]));
}
__device__ __forceinline__ void cp16(uint32_t* smem_dst, const void* gsrc) {
    uint32_t s = (uint32_t)__cvta_generic_to_shared(smem_dst);
    asm volatile("cp.async.cg.shared.global [%0], [%1], 16;\n"
                 :: "r"(s), "l"(gsrc));
}

// ---------------- LayerNorm: one warp per token ----------------
__global__ void ln_kernel(const float* __restrict__ z,
                          const float* __restrict__ gamma,
                          const float* __restrict__ beta) {
    int warp = threadIdx.x >> 5, lane = threadIdx.x & 31;
    int t = blockIdx.x * 8 + warp;
    const float4 v = *(const float4*)(z + (size_t)t * C + lane * 4);
    float s = v.x + v.y + v.z + v.w;
    #pragma unroll
    for (int o = 16; o; o >>= 1) s += __shfl_xor_sync(0xffffffffu, s, o);
    float mu = s * (1.0f / C);
    float d0 = v.x - mu, d1 = v.y - mu, d2 = v.z - mu, d3 = v.w - mu;
    float vs = d0*d0 + d1*d1 + d2*d2 + d3*d3;
    #pragma unroll
    for (int o = 16; o; o >>= 1) vs += __shfl_xor_sync(0xffffffffu, vs, o);
    float r = rsqrtf(vs * (1.0f / C) + 1e-5f);
    float4 gm = *(const float4*)(gamma + lane * 4);
    float4 bt = *(const float4*)(beta + lane * 4);
    float4 out;
    out.x = d0 * r * gm.x + bt.x;
    out.y = d1 * r * gm.y + bt.y;
    out.z = d2 * r * gm.z + bt.z;
    out.w = d3 * r * gm.w + bt.w;
    *(float4*)(g_lnz + (size_t)t * C + lane * 4) = out;
}

// ------- weight prep: split + pack + transpose: g_wp*[mat][n][k2] -------
__global__ void wprep_kernel(W5 ws) {
    int mat = blockIdx.y;
    int idx = blockIdx.x * 256 + threadIdx.x;   // 8192 per matrix
    int n = idx >> 6, k2 = idx & 63;
    const float* W = ws.w[mat];
    float w0 = W[(2 * k2) * C + n];
    float w1 = W[(2 * k2 + 1) * C + n];
    float h0 = bf16val(w0), h1 = bf16val(w1);
    g_wph[mat * 8192 + n * 64 + k2] = bf16pair(w0, w1);
    g_wpl[mat * 8192 + n * 64 + k2] = bf16pair(w0 - h0, w1 - h1);
}

// ---------------- fused bf16-3x GEMM: stage X once, stream W ----------------
// X: [NT,128] fp32, split in-kernel. W: pre-packed slots. Y: up to 4 outputs.
#define XW 68                    // padded row stride (words of pairs domain = 64)
#define XPLANE (128 * XW)        // 8704 words
#define WBUF (2 * XPLANE)        // hi+lo planes per W buffer
#define GEMM_SMEM ((2 * XPLANE + 2 * WBUF) * 4)   // 208896 B

__global__ void __launch_bounds__(256, 1)
gemm_fused(const float* __restrict__ X, int slot0, int nmat, Y4 ys, int sigmask) {
    extern __shared__ uint32_t sm4[];
    uint32_t* Xh2 = sm4;             // [128][XW]
    uint32_t* Xl2 = sm4 + XPLANE;
    uint32_t* Wb  = sm4 + 2 * XPLANE; // two buffers of WBUF

    int tid = threadIdx.x;
    int warp = tid >> 5, lane = tid & 31;
    int g = lane >> 2, t = lane & 3;
    int wm = warp >> 1, wn = warp & 1;
    int row0 = blockIdx.x * 128;

    auto issueW = [&](int s, int buf) {
        uint32_t* wb = Wb + buf * WBUF;
        #pragma unroll
        for (int i = 0; i < 16; i++) {
            int id = tid + i * 256;          // 0..4095
            int plane = id >> 11, r = id & 2047;
            int n = r >> 4, q = r & 15;
            const uint32_t* src =
                (plane ? g_wpl : g_wph) + (slot0 + s) * 8192 + n * 64 + q * 4;
            cp16(wb + plane * XPLANE + n * XW + q * 4, src);
        }
    };

    // stage X (split+pack) while W0 streams in
    issueW(0, 0);
    asm volatile("cp.async.commit_group;\n");
    #pragma unroll
    for (int i = 0; i < 16; i++) {
        int id = tid + i * 256;              // 4096 float4
        int row = id >> 5, c4 = id & 31;
        float4 v = *(const float4*)(X + (size_t)(row0 + row) * C + c4 * 4);
        float h0 = bf16val(v.x), h1 = bf16val(v.y);
        float h2 = bf16val(v.z), h3 = bf16val(v.w);
        uint32_t* xh = Xh2 + row * XW + c4 * 2;
        uint32_t* xl = Xl2 + row * XW + c4 * 2;
        xh[0] = bf16pair(v.x, v.y);
        xh[1] = bf16pair(v.z, v.w);
        xl[0] = bf16pair(v.x - h0, v.y - h1);
        xl[1] = bf16pair(v.z - h2, v.w - h3);
    }

    #pragma unroll 1
    for (int s = 0; s < nmat; s++) {
        if (s + 1 < nmat) {
            issueW(s + 1, (s + 1) & 1);
            asm volatile("cp.async.commit_group;\n");
            asm volatile("cp.async.wait_group 1;\n");
        } else {
            asm volatile("cp.async.wait_group 0;\n");
        }
        __syncthreads();

        uint32_t* Wh2 = Wb + (s & 1) * WBUF;
        uint32_t* Wl2 = Wh2 + XPLANE;

        float c[2][8][4];
        #pragma unroll
        for (int mb = 0; mb < 2; mb++)
            #pragma unroll
            for (int nb = 0; nb < 8; nb++)
                #pragma unroll
                for (int r = 0; r < 4; r++) c[mb][nb][r] = 0.0f;

        #pragma unroll
        for (int ks = 0; ks < 8; ks++) {
            int kb = ks * 8;
            uint32_t bh[8][2], bl[8][2];
            #pragma unroll
            for (int nb = 0; nb < 8; nb++) {
                int n = wn * 64 + nb * 8 + g;
                bh[nb][0] = Wh2[n * XW + kb + t];
                bh[nb][1] = Wh2[n * XW + kb + t + 4];
                bl[nb][0] = Wl2[n * XW + kb + t];
                bl[nb][1] = Wl2[n * XW + kb + t + 4];
            }
            #pragma unroll
            for (int mb = 0; mb < 2; mb++) {
                int r = wm * 32 + mb * 16 + g;
                uint32_t ah[4], al[4];
                ah[0] = Xh2[r * XW + kb + t];
                ah[1] = Xh2[(r + 8) * XW + kb + t];
                ah[2] = Xh2[r * XW + kb + t + 4];
                ah[3] = Xh2[(r + 8) * XW + kb + t + 4];
                al[0] = Xl2[r * XW + kb + t];
                al[1] = Xl2[(r + 8) * XW + kb + t];
                al[2] = Xl2[r * XW + kb + t + 4];
                al[3] = Xl2[(r + 8) * XW + kb + t + 4];
                #pragma unroll
                for (int nb = 0; nb < 8; nb++) {
                    mma_bf16(c[mb][nb], ah, bh[nb]);
                    mma_bf16(c[mb][nb], ah, bl[nb]);
                    mma_bf16(c[mb][nb], al, bh[nb]);
                }
            }
        }

        float* Y = ys.p[s];
        int sg = (sigmask >> s) & 1;
        #pragma unroll
        for (int mb = 0; mb < 2; mb++) {
            int r0 = row0 + wm * 32 + mb * 16 + g;
            #pragma unroll
            for (int nb = 0; nb < 8; nb++) {
                int col = wn * 64 + nb * 8 + 2 * t;
                float v0 = c[mb][nb][0], v1 = c[mb][nb][1];
                float v2 = c[mb][nb][2], v3 = c[mb][nb][3];
                if (sg) {
                    v0 = 1.0f / (1.0f + __expf(-v0));
                    v1 = 1.0f / (1.0f + __expf(-v1));
                    v2 = 1.0f / (1.0f + __expf(-v2));
                    v3 = 1.0f / (1.0f + __expf(-v3));
                }
                *(float2*)(Y + (size_t)r0 * C + col) = make_float2(v0, v1);
                *(float2*)(Y + (size_t)(r0 + 8) * C + col) = make_float2(v2, v3);
            }
        }
        __syncthreads();
    }
}

// ------- bias = lnz @ Wb, written TRANSPOSED as g_bt[h][k][j] -------
__global__ void bias_kernel(const float* __restrict__ Wb) {
    __shared__ float wb[C * H];
    int tid = threadIdx.x;
    wb[tid] = Wb[tid];
    wb[tid + 256] = Wb[tid + 256];
    __syncthreads();
    int warp = tid >> 5, lane = tid & 31;
    int t = blockIdx.x * 8 + warp;
    float4 zv = *(const float4*)(g_lnz + (size_t)t * C + lane * 4);
    int c0 = lane * 4;
    int j = t >> 8, k = t & 255;
    #pragma unroll
    for (int h = 0; h < H; h++) {
        float p = zv.x * wb[(c0 + 0) * H + h] + zv.y * wb[(c0 + 1) * H + h] +
                  zv.z * wb[(c0 + 2) * H + h] + zv.w * wb[(c0 + 3) * H + h];
        #pragma unroll
        for (int o = 16; o; o >>= 1) p += __shfl_xor_sync(0xffffffffu, p, o);
        if (lane == 0) g_bt[((size_t)h * N + k) * N + j] = p;
    }
}

// ---------------- tensor-core attention (round-4, plain fp32 output) ----------------
#define KTS 260
#define VST 36
#define PST 36
#define ATTN_SMEM ((2 * 32 * KTS + 256 * VST + 8 * 32 * PST) * 4)

__global__ void __launch_bounds__(256)
attn_mma() {
    extern __shared__ float sm[];
    float* Kht = sm;
    float* Klt = Kht + 32 * KTS;
    float* Vs  = Klt + 32 * KTS;
    float* Ps  = Vs + 256 * VST;

    int i = blockIdx.x, h = blockIdx.y;
    int tid = threadIdx.x;
    int w = tid >> 5, lane = tid & 31;
    int g = lane >> 2, t = lane & 3;
    size_t base = (size_t)i * N;
    int coff = h * D;
    float* Pw = Ps + w * 32 * PST;
    const float sc = 0.17677669529663687f;

    #pragma unroll
    for (int it = 0; it < 8; it++) {
        int idx = tid + it * 256;
        int tok = idx >> 3, f = idx & 7;
        float4 kv = *(const float4*)(g_k + (base + tok) * C + coff + f * 4);
        uint32_t hx, lx;
        split_tf32(kv.x, hx, lx);
        Kht[(f*4+0)*KTS + tok] = __uint_as_float(hx);
        Klt[(f*4+0)*KTS + tok] = __uint_as_float(lx);
        split_tf32(kv.y, hx, lx);
        Kht[(f*4+1)*KTS + tok] = __uint_as_float(hx);
        Klt[(f*4+1)*KTS + tok] = __uint_as_float(lx);
        split_tf32(kv.z, hx, lx);
        Kht[(f*4+2)*KTS + tok] = __uint_as_float(hx);
        Klt[(f*4+2)*KTS + tok] = __uint_as_float(lx);
        split_tf32(kv.w, hx, lx);
        Kht[(f*4+3)*KTS + tok] = __uint_as_float(hx);
        Klt[(f*4+3)*KTS + tok] = __uint_as_float(lx);

        float4 vv = *(const float4*)(g_v + (base + tok) * C + coff + f * 4);
        float4 vt;
        vt.x = __uint_as_float(to_tf32(vv.x));
        vt.y = __uint_as_float(to_tf32(vv.y));
        vt.z = __uint_as_float(to_tf32(vv.z));
        vt.w = __uint_as_float(to_tf32(vv.w));
        *(float4*)(Vs + tok * VST + f * 4) = vt;
    }

    int jb = w * 32;
    uint32_t qh[2][4][4], ql[2][4][4];
    #pragma unroll
    for (int mb = 0; mb < 2; mb++) {
        int r1 = jb + mb * 16 + g, r2 = r1 + 8;
        #pragma unroll
        for (int ds = 0; ds < 4; ds++) {
            int c1 = coff + ds * 8 + t, c2 = c1 + 4;
            float q0 = g_q[(base + r1) * C + c1] * sc;
            float q1 = g_q[(base + r2) * C + c1] * sc;
            float q2 = g_q[(base + r1) * C + c2] * sc;
            float q3 = g_q[(base + r2) * C + c2] * sc;
            split_tf32(q0, qh[mb][ds][0], ql[mb][ds][0]);
            split_tf32(q1, qh[mb][ds][1], ql[mb][ds][1]);
            split_tf32(q2, qh[mb][ds][2], ql[mb][ds][2]);
            split_tf32(q3, qh[mb][ds][3], ql[mb][ds][3]);
        }
    }
    __syncthreads();

    float o[2][4][4];
    #pragma unroll
    for (int mb = 0; mb < 2; mb++)
        #pragma unroll
        for (int nb = 0; nb < 4; nb++)
            #pragma unroll
            for (int r = 0; r < 4; r++) o[mb][nb][r] = 0.0f;
    float lA[2] = {0.f, 0.f}, lB[2] = {0.f, 0.f};

    const float* bth = g_bt + (size_t)h * NT;

    for (int ch = 0; ch < 8; ch++) {
        int tok0 = ch * 32;
        float s[2][4][4];
        #pragma unroll
        for (int mb = 0; mb < 2; mb++)
            #pragma unroll
            for (int nt = 0; nt < 4; nt++)
                #pragma unroll
                for (int r = 0; r < 4; r++) s[mb][nt][r] = 0.0f;

        #pragma unroll
        for (int nt = 0; nt < 4; nt++) {
            int tokn = tok0 + nt * 8 + g;
            #pragma unroll
            for (int ds = 0; ds < 4; ds++) {
                uint32_t bh2[2], bl2[2];
                bh2[0] = __float_as_uint(Kht[(ds*8 + t) * KTS + tokn]);
                bh2[1] = __float_as_uint(Kht[(ds*8 + t + 4) * KTS + tokn]);
                bl2[0] = __float_as_uint(Klt[(ds*8 + t) * KTS + tokn]);
                bl2[1] = __float_as_uint(Klt[(ds*8 + t + 4) * KTS + tokn]);
                #pragma unroll
                for (int mb = 0; mb < 2; mb++) {
                    mma_tf32(s[mb][nt], qh[mb][ds], bh2);
                    mma_tf32(s[mb][nt], qh[mb][ds], bl2);
                    mma_tf32(s[mb][nt], ql[mb][ds], bh2);
                }
            }
        }
        #pragma unroll
        for (int mb = 0; mb < 2; mb++) {
            int j1 = jb + mb * 16 + g, j2 = j1 + 8;
            #pragma unroll
            for (int nt = 0; nt < 4; nt++) {
                int k0 = tok0 + nt * 8 + 2 * t;
                float b00 = bth[(size_t)k0 * N + j1];
                float b01 = bth[(size_t)(k0 + 1) * N + j1];
                float b10 = bth[(size_t)k0 * N + j2];
                float b11 = bth[(size_t)(k0 + 1) * N + j2];
                float p0 = __expf(s[mb][nt][0] + b00);
                float p1 = __expf(s[mb][nt][1] + b01);
                float p2 = __expf(s[mb][nt][2] + b10);
                float p3 = __expf(s[mb][nt][3] + b11);
                lA[mb] += p0 + p1;
                lB[mb] += p2 + p3;
                int cc = nt * 8 + 2 * t;
                Pw[(mb*16 + g) * PST + cc]     = __uint_as_float(to_tf32(p0));
                Pw[(mb*16 + g) * PST + cc + 1] = __uint_as_float(to_tf32(p1));
                Pw[(mb*16 + 8 + g) * PST + cc]     = __uint_as_float(to_tf32(p2));
                Pw[(mb*16 + 8 + g) * PST + cc + 1] = __uint_as_float(to_tf32(p3));
            }
        }
        __syncwarp();
        #pragma unroll
        for (int ks = 0; ks < 4; ks++) {
            uint32_t pa[2][4];
            #pragma unroll
            for (int mb = 0; mb < 2; mb++) {
                pa[mb][0] = __float_as_uint(Pw[(mb*16 + g) * PST + ks*8 + t]);
                pa[mb][1] = __float_as_uint(Pw[(mb*16 + 8 + g) * PST + ks*8 + t]);
                pa[mb][2] = __float_as_uint(Pw[(mb*16 + g) * PST + ks*8 + t + 4]);
                pa[mb][3] = __float_as_uint(Pw[(mb*16 + 8 + g) * PST + ks*8 + t + 4]);
            }
            #pragma unroll
            for (int nb = 0; nb < 4; nb++) {
                uint32_t vb[2];
                vb[0] = __float_as_uint(Vs[(tok0 + ks*8 + t) * VST + nb*8 + g]);
                vb[1] = __float_as_uint(Vs[(tok0 + ks*8 + t + 4) * VST + nb*8 + g]);
                #pragma unroll
                for (int mb = 0; mb < 2; mb++)
                    mma_tf32(o[mb][nb], pa[mb], vb);
            }
        }
        __syncwarp();
    }

    #pragma unroll
    for (int mb = 0; mb < 2; mb++) {
        lA[mb] += __shfl_xor_sync(0xffffffffu, lA[mb], 1);
        lA[mb] += __shfl_xor_sync(0xffffffffu, lA[mb], 2);
        lB[mb] += __shfl_xor_sync(0xffffffffu, lB[mb], 1);
        lB[mb] += __shfl_xor_sync(0xffffffffu, lB[mb], 2);
        float inv1 = 1.0f / lA[mb], inv2 = 1.0f / lB[mb];
        int j1 = jb + mb * 16 + g, j2 = j1 + 8;
        #pragma unroll
        for (int nb = 0; nb < 4; nb++) {
            int d = nb * 8 + 2 * t;
            float2 g1 = *(const float2*)(g_g + (base + j1) * C + coff + d);
            float2 g2 = *(const float2*)(g_g + (base + j2) * C + coff + d);
            float2 o1, o2;
            o1.x = g1.x * o[mb][nb][0] * inv1;
            o1.y = g1.y * o[mb][nb][1] * inv1;
            o2.x = g2.x * o[mb][nb][2] * inv2;
            o2.y = g2.y * o[mb][nb][3] * inv2;
            *(float2*)(g_o + (base + j1) * C + coff + d) = o1;
            *(float2*)(g_o + (base + j2) * C + coff + d) = o2;
        }
    }
}

extern "C" void kernel_launch(void* const* d_in, const int* in_sizes, int n_in,
                              void* d_out, int out_size) {
    const float* z     = (const float*)d_in[0];
    const float* gamma = (const float*)d_in[1];
    const float* beta  = (const float*)d_in[2];
    const float* Wq    = (const float*)d_in[3];
    const float* Wk    = (const float*)d_in[4];
    const float* Wv    = (const float*)d_in[5];
    const float* Wb    = (const float*)d_in[6];
    const float* Wg    = (const float*)d_in[7];
    const float* Wout  = (const float*)d_in[8];
    float* out = (float*)d_out;

    void *p_lnz, *p_q, *p_k, *p_v, *p_g, *p_o;
    cudaGetSymbolAddress(&p_lnz, g_lnz);
    cudaGetSymbolAddress(&p_q, g_q);
    cudaGetSymbolAddress(&p_k, g_k);
    cudaGetSymbolAddress(&p_v, g_v);
    cudaGetSymbolAddress(&p_g, g_g);
    cudaGetSymbolAddress(&p_o, g_o);

    cudaFuncSetAttribute(gemm_fused,
                         cudaFuncAttributeMaxDynamicSharedMemorySize, GEMM_SMEM);
    cudaFuncSetAttribute(attn_mma,
                         cudaFuncAttributeMaxDynamicSharedMemorySize, ATTN_SMEM);

    ln_kernel<<<NT / 8, 256>>>(z, gamma, beta);
    W5 ws; ws.w[0] = Wq; ws.w[1] = Wk; ws.w[2] = Wv; ws.w[3] = Wg; ws.w[4] = Wout;
    wprep_kernel<<<dim3(32, 5), 256>>>(ws);

    Y4 yq; yq.p[0] = (float*)p_q; yq.p[1] = (float*)p_k;
    yq.p[2] = (float*)p_v; yq.p[3] = (float*)p_g;
    gemm_fused<<<NT / 128, 256, GEMM_SMEM>>>((const float*)p_lnz, 0, 4, yq, 0x8);

    bias_kernel<<<NT / 8, 256>>>(Wb);
    attn_mma<<<dim3(N, H), 256, ATTN_SMEM>>>();

    Y4 yo; yo.p[0] = out; yo.p[1] = yo.p[2] = yo.p[3] = nullptr;
    gemm_fused<<<NT / 128, 256, GEMM_SMEM>>>((const float*)p_o, 4, 1, yo, 0);
}